// round 6
// baseline (speedup 1.0000x reference)
#include <cuda_runtime.h>
#include <cuda_bf16.h>
#include <cstdint>

// ---------------- problem constants ----------------
#define BATCH  1024
#define INSZ   512
#define UNITS  512
#define K12    12
#define KDIM   (INSZ * K12)      // 6144
#define KSPLIT 4
#define KPER   (KDIM / KSPLIT)   // 1536
#define TK     64                // K columns per stage (128 B/row bf16)
#define STAGES (KPER / TK)       // 24
#define PIPE   4                 // cp.async pipeline depth

// ---------------- scratch (static device globals; no allocation) ----------------
__device__ __align__(16) __nv_bfloat16 g_A[(size_t)BATCH * KDIM];     // 12.6 MB
__device__ __align__(16) __nv_bfloat16 g_Bt[(size_t)UNITS * KDIM];    // 6.3 MB

// ---------------- helpers ----------------
__device__ __forceinline__ uint32_t smem_u32(const void* p) {
    uint32_t a;
    asm("{ .reg .u64 t; cvta.to.shared.u64 t, %1; cvt.u32.u64 %0, t; }" : "=r"(a) : "l"(p));
    return a;
}
__device__ __forceinline__ uint32_t swz(uint32_t off) { return off ^ ((off >> 3) & 0x70); }

__device__ __forceinline__ void cp_async16(uint32_t saddr, const void* g) {
    asm volatile("cp.async.cg.shared.global [%0], [%1], 16;" :: "r"(saddr), "l"(g) : "memory");
}
#define CP_COMMIT() asm volatile("cp.async.commit_group;" ::: "memory")
#define CP_WAIT(N)  asm volatile("cp.async.wait_group %0;" :: "n"(N) : "memory")

__device__ __forceinline__ void ldsm_x4(uint32_t& r0, uint32_t& r1, uint32_t& r2, uint32_t& r3,
                                        uint32_t addr) {
    asm volatile("ldmatrix.sync.aligned.m8n8.x4.shared.b16 {%0,%1,%2,%3}, [%4];"
                 : "=r"(r0), "=r"(r1), "=r"(r2), "=r"(r3) : "r"(addr));
}
__device__ __forceinline__ void mma16816(float* c, const uint32_t* a, uint32_t b0, uint32_t b1) {
    asm volatile("mma.sync.aligned.m16n8k16.row.col.f32.bf16.bf16.f32 "
                 "{%0,%1,%2,%3}, {%4,%5,%6,%7}, {%8,%9}, {%0,%1,%2,%3};"
                 : "+f"(c[0]), "+f"(c[1]), "+f"(c[2]), "+f"(c[3])
                 : "r"(a[0]), "r"(a[1]), "r"(a[2]), "r"(a[3]), "r"(b0), "r"(b1));
}
__device__ __forceinline__ void red_add_f32(float* p, float v) {
    asm volatile("red.global.add.f32 [%0], %1;" :: "l"(p), "f"(v) : "memory");
}
__device__ __forceinline__ unsigned pkb(__nv_bfloat16 a, __nv_bfloat16 b) {
    return (unsigned)__bfloat16_as_ushort(a) | ((unsigned)__bfloat16_as_ushort(b) << 16);
}

// ---------------- kernel 1: A[b, i*12 + c] = {8 cubic B-spline bases, shi, shi, slo, 0} ----------------
__global__ void build_A(const float* __restrict__ X) {
    int lin = blockIdx.x * blockDim.x + threadIdx.x;
    if (lin >= BATCH * INSZ) return;
    float x = X[lin];

    // uniform knots t_j = -2.2 + 0.4*j, j = 0..11  (GRID=5, ORDER=3, range [-1,1])
    float bb[11];
#pragma unroll
    for (int j = 0; j < 11; j++) {
        float tj = -2.2f + 0.4f * j;
        bb[j] = (x >= tj && x < tj + 0.4f) ? 1.f : 0.f;
    }
#pragma unroll
    for (int k = 1; k <= 3; k++) {
        float inv = 1.f / (0.4f * k);
#pragma unroll
        for (int j = 0; j < 11 - k; j++) {
            float tj = -2.2f + 0.4f * j;
            float tjk1 = -2.2f + 0.4f * (j + k + 1);
            bb[j] = (x - tj) * inv * bb[j] + (tjk1 - x) * inv * bb[j + 1];
        }
    }
    float s = x / (1.f + expf(-x));  // silu
    __nv_bfloat16 shi = __float2bfloat16(s);
    __nv_bfloat16 slo = __float2bfloat16(s - __bfloat162float(shi));

    __nv_bfloat16 h[8];
#pragma unroll
    for (int j = 0; j < 8; j++) h[j] = __float2bfloat16(bb[j]);

    uint2* dst = (uint2*)(g_A + (size_t)lin * K12);
    dst[0] = make_uint2(pkb(h[0], h[1]), pkb(h[2], h[3]));
    dst[1] = make_uint2(pkb(h[4], h[5]), pkb(h[6], h[7]));
    dst[2] = make_uint2(pkb(shi, shi), pkb(slo, __float2bfloat16(0.f)));
}

// ---------------- kernel 2: Bt[o, i*12 + c] = {scale*W_k (k=0..7), schi, sclo, schi, 0} ----------------
__global__ void build_Bt(const float* __restrict__ Wk, const float* __restrict__ scale) {
    int lin = blockIdx.x * blockDim.x + threadIdx.x;
    if (lin >= UNITS * INSZ) return;
    int o = lin & (UNITS - 1);
    int i = lin >> 9;
    float sc = scale[(size_t)i * UNITS + o];

    __nv_bfloat16 c[8];
#pragma unroll
    for (int k = 0; k < 8; k++)
        c[k] = __float2bfloat16(sc * Wk[((size_t)i * 8 + k) * UNITS + o]);
    __nv_bfloat16 schi = __float2bfloat16(sc);
    __nv_bfloat16 sclo = __float2bfloat16(sc - __bfloat162float(schi));

    uint2* dst = (uint2*)(g_Bt + (size_t)o * KDIM + i * K12);
    dst[0] = make_uint2(pkb(c[0], c[1]), pkb(c[2], c[3]));
    dst[1] = make_uint2(pkb(c[4], c[5]), pkb(c[6], c[7]));
    dst[2] = make_uint2(pkb(schi, sclo), pkb(schi, __float2bfloat16(0.f)));
}

// ---------------- kernel 3: out[b,o] = bias[o] (atomic accumulation base) ----------------
__global__ void init_out(const float* __restrict__ bias, float* __restrict__ out) {
    int idx = (blockIdx.x * blockDim.x + threadIdx.x) * 4;
    if (idx >= BATCH * UNITS) return;
    *(float4*)(out + idx) = *(const float4*)(bias + (idx & (UNITS - 1)));
}

// ---------------- kernel 4: split-K bf16 mma.sync GEMM (16 warps), epilogue red.global.add ----------------
// CTA tile 128x128, warp tile 32x32 (4x4 warps), K-stage 64, 4-stage cp.async pipeline.
// RACE-FREE single barrier per stage: WAIT(s) -> barrier -> ISSUE(s+3) -> COMPUTE(s).
__global__ __launch_bounds__(512, 1)
void kan_gemm(float* __restrict__ out) {
    extern __shared__ char dyn[];
    const uint32_t base = smem_u32(dyn);   // PIPE stages of [A 16KB | B 16KB]

    const int t   = threadIdx.x;
    const int wid = t >> 5, lane = t & 31;
    const int wm  = wid & 3;               // 4 warp-rows  -> 32 m each
    const int wn  = wid >> 2;              // 4 warp-cols  -> 32 n each
    const int m0  = blockIdx.y * 128;
    const int n0  = blockIdx.x * 128;
    const int kbase = blockIdx.z * KPER;

    // ---- cp.async addressing: thread -> (row = t>>3 in 0..63, chunk = t&7) ----
    const int crow = t >> 3;               // 0..63
    const int cchk = t & 7;                // 16B chunk (k-offset cchk*8 elems)
    const __nv_bfloat16* gA = g_A  + (size_t)(m0 + crow) * KDIM + kbase + cchk * 8;
    const __nv_bfloat16* gB = g_Bt + (size_t)(n0 + crow) * KDIM + kbase + cchk * 8;

    auto stage_base = [&](int s) { return base + (uint32_t)(s % PIPE) * 32768u; };

    auto issue_stage = [&](int s) {
        uint32_t sb = stage_base(s);
        const __nv_bfloat16* pa = gA + s * TK;
        const __nv_bfloat16* pb = gB + s * TK;
#pragma unroll
        for (int q = 0; q < 2; q++) {
            uint32_t so = swz((uint32_t)(crow + q * 64) * 128u + (uint32_t)cchk * 16u);
            cp_async16(sb + so,          pa + (size_t)(q * 64) * KDIM);
            cp_async16(sb + 16384u + so, pb + (size_t)(q * 64) * KDIM);
        }
    };

    // ---- prologue: PIPE-1 stages in flight ----
#pragma unroll
    for (int s = 0; s < PIPE - 1; s++) { issue_stage(s); CP_COMMIT(); }

    // ---- per-lane ldmatrix offsets (within stage tile) ----
    const uint32_t a_row = (uint32_t)(wm * 32 + (lane & 15));
    const uint32_t a_kb  = (uint32_t)((lane >> 4) * 16);
    const uint32_t b_row = (uint32_t)(wn * 32 + (lane & 7) + ((lane >> 4) & 1) * 8);
    const uint32_t b_kb  = (uint32_t)(((lane >> 3) & 1) * 16);

    float acc[2][4][4];
#pragma unroll
    for (int mi = 0; mi < 2; mi++)
#pragma unroll
        for (int ni = 0; ni < 4; ni++)
#pragma unroll
            for (int r = 0; r < 4; r++) acc[mi][ni][r] = 0.f;

    for (int s = 0; s < STAGES; ++s) {
        CP_WAIT(PIPE - 2);
        __syncthreads();           // stage-s data visible; stage-(s-1) reads complete

        if (s + PIPE - 1 < STAGES) issue_stage(s + PIPE - 1);
        CP_COMMIT();

        uint32_t sa = stage_base(s);
        uint32_t sbB = sa + 16384u;

        // ---- load the stage's fragments into registers (hide LDSM latency) ----
        uint32_t a[2][4][4];   // [mi][kk][reg]
        uint32_t b[2][4][4];   // [g][kk][reg]  (2 n16 groups = 32 n)
#pragma unroll
        for (int kk = 0; kk < 4; kk++) {
#pragma unroll
            for (int mi = 0; mi < 2; mi++)
                ldsm_x4(a[mi][kk][0], a[mi][kk][1], a[mi][kk][2], a[mi][kk][3],
                        sa + swz((a_row + mi * 16) * 128u + a_kb + kk * 32u));
#pragma unroll
            for (int g = 0; g < 2; g++)
                ldsm_x4(b[g][kk][0], b[g][kk][1], b[g][kk][2], b[g][kk][3],
                        sbB + swz((b_row + g * 16) * 128u + b_kb + kk * 32u));
        }

        // ---- 32 back-to-back HMMAs per warp ----
#pragma unroll
        for (int kk = 0; kk < 4; kk++)
#pragma unroll
            for (int mi = 0; mi < 2; mi++)
#pragma unroll
                for (int g = 0; g < 2; g++) {
                    mma16816(acc[mi][2 * g + 0], a[mi][kk], b[g][kk][0], b[g][kk][1]);
                    mma16816(acc[mi][2 * g + 1], a[mi][kk], b[g][kk][2], b[g][kk][3]);
                }
    }

    // ---- epilogue: atomic-accumulate fp32 tile into out (pre-initialized with bias) ----
    const int er = lane >> 2;          // 0..7
    const int ec = (lane & 3) * 2;     // 0,2,4,6
#pragma unroll
    for (int mi = 0; mi < 2; mi++) {
#pragma unroll
        for (int ni = 0; ni < 4; ni++) {
            int row = m0 + wm * 32 + mi * 16 + er;
            int col = n0 + wn * 32 + ni * 8 + ec;
            float* p0 = out + (size_t)row * UNITS + col;
            red_add_f32(p0 + 0, acc[mi][ni][0]);
            red_add_f32(p0 + 1, acc[mi][ni][1]);
            float* p1 = p0 + 8 * UNITS;
            red_add_f32(p1 + 0, acc[mi][ni][2]);
            red_add_f32(p1 + 1, acc[mi][ni][3]);
        }
    }
}

// ---------------- launch ----------------
extern "C" void kernel_launch(void* const* d_in, const int* in_sizes, int n_in,
                              void* d_out, int out_size) {
    const float* x    = (const float*)d_in[0];  // (1024, 512)
    const float* wk   = (const float*)d_in[1];  // (512, 8, 512)
    const float* sc   = (const float*)d_in[2];  // (512, 512)
    const float* bias = (const float*)d_in[3];  // (512,)
    float* out = (float*)d_out;                 // (1024, 512)

    build_A<<<(BATCH * INSZ) / 256, 256>>>(x);
    build_Bt<<<(UNITS * INSZ) / 256, 256>>>(wk, sc);
    init_out<<<(BATCH * UNITS / 4) / 256, 256>>>(bias, out);

    const int dsmem = PIPE * 32768;  // 128 KB: 4 stages of [A 16KB | B 16KB]
    cudaFuncSetAttribute(kan_gemm, cudaFuncAttributeMaxDynamicSharedMemorySize, dsmem);
    kan_gemm<<<dim3(UNITS / 128, BATCH / 128, KSPLIT), 512, dsmem>>>(out);
}

// round 7
// speedup vs baseline: 1.2183x; 1.2183x over previous
#include <cuda_runtime.h>
#include <cuda_bf16.h>
#include <cstdint>

// ---------------- problem constants ----------------
#define BATCH  1024
#define INSZ   512
#define UNITS  512
#define K12    12
#define KDIM   (INSZ * K12)      // 6144
#define KSPLIT 4
#define KPER   (KDIM / KSPLIT)   // 1536
#define TK     64                // K columns per stage (128 B/row bf16)
#define STAGES (KPER / TK)       // 24
#define PIPE   4                 // cp.async pipeline depth

// ---------------- scratch (static device globals; no allocation) ----------------
__device__ __align__(16) __nv_bfloat16 g_A[(size_t)BATCH * KDIM];     // 12.6 MB
__device__ __align__(16) __nv_bfloat16 g_Bt[(size_t)UNITS * KDIM];    // 6.3 MB

// ---------------- helpers ----------------
__device__ __forceinline__ uint32_t smem_u32(const void* p) {
    uint32_t a;
    asm("{ .reg .u64 t; cvta.to.shared.u64 t, %1; cvt.u32.u64 %0, t; }" : "=r"(a) : "l"(p));
    return a;
}
__device__ __forceinline__ uint32_t swz(uint32_t off) { return off ^ ((off >> 3) & 0x70); }

__device__ __forceinline__ void cp_async16(uint32_t saddr, const void* g) {
    asm volatile("cp.async.cg.shared.global [%0], [%1], 16;" :: "r"(saddr), "l"(g) : "memory");
}
#define CP_COMMIT() asm volatile("cp.async.commit_group;" ::: "memory")
#define CP_WAIT(N)  asm volatile("cp.async.wait_group %0;" :: "n"(N) : "memory")

__device__ __forceinline__ void ldsm_x4(uint32_t& r0, uint32_t& r1, uint32_t& r2, uint32_t& r3,
                                        uint32_t addr) {
    asm volatile("ldmatrix.sync.aligned.m8n8.x4.shared.b16 {%0,%1,%2,%3}, [%4];"
                 : "=r"(r0), "=r"(r1), "=r"(r2), "=r"(r3) : "r"(addr));
}
__device__ __forceinline__ void mma16816(float* c, const uint32_t* a, uint32_t b0, uint32_t b1) {
    asm volatile("mma.sync.aligned.m16n8k16.row.col.f32.bf16.bf16.f32 "
                 "{%0,%1,%2,%3}, {%4,%5,%6,%7}, {%8,%9}, {%0,%1,%2,%3};"
                 : "+f"(c[0]), "+f"(c[1]), "+f"(c[2]), "+f"(c[3])
                 : "r"(a[0]), "r"(a[1]), "r"(a[2]), "r"(a[3]), "r"(b0), "r"(b1));
}
__device__ __forceinline__ void red_add_f32(float* p, float v) {
    asm volatile("red.global.add.f32 [%0], %1;" :: "l"(p), "f"(v) : "memory");
}
__device__ __forceinline__ unsigned pkb(__nv_bfloat16 a, __nv_bfloat16 b) {
    return (unsigned)__bfloat16_as_ushort(a) | ((unsigned)__bfloat16_as_ushort(b) << 16);
}

// ---------------- kernel 1: A[b, i*12 + c] = {8 cubic B-spline bases, shi, shi, slo, 0} ----------------
__global__ void build_A(const float* __restrict__ X) {
    int lin = blockIdx.x * blockDim.x + threadIdx.x;
    if (lin >= BATCH * INSZ) return;
    float x = X[lin];

    // uniform knots t_j = -2.2 + 0.4*j, j = 0..11  (GRID=5, ORDER=3, range [-1,1])
    float bb[11];
#pragma unroll
    for (int j = 0; j < 11; j++) {
        float tj = -2.2f + 0.4f * j;
        bb[j] = (x >= tj && x < tj + 0.4f) ? 1.f : 0.f;
    }
#pragma unroll
    for (int k = 1; k <= 3; k++) {
        float inv = 1.f / (0.4f * k);
#pragma unroll
        for (int j = 0; j < 11 - k; j++) {
            float tj = -2.2f + 0.4f * j;
            float tjk1 = -2.2f + 0.4f * (j + k + 1);
            bb[j] = (x - tj) * inv * bb[j] + (tjk1 - x) * inv * bb[j + 1];
        }
    }
    float s = x / (1.f + expf(-x));  // silu
    __nv_bfloat16 shi = __float2bfloat16(s);
    __nv_bfloat16 slo = __float2bfloat16(s - __bfloat162float(shi));

    __nv_bfloat16 h[8];
#pragma unroll
    for (int j = 0; j < 8; j++) h[j] = __float2bfloat16(bb[j]);

    uint2* dst = (uint2*)(g_A + (size_t)lin * K12);
    dst[0] = make_uint2(pkb(h[0], h[1]), pkb(h[2], h[3]));
    dst[1] = make_uint2(pkb(h[4], h[5]), pkb(h[6], h[7]));
    dst[2] = make_uint2(pkb(shi, shi), pkb(slo, __float2bfloat16(0.f)));
}

// ---------------- kernel 2: Bt[o, i*12 + c] = {scale*W_k (k=0..7), schi, sclo, schi, 0} ----------------
__global__ void build_Bt(const float* __restrict__ Wk, const float* __restrict__ scale) {
    int lin = blockIdx.x * blockDim.x + threadIdx.x;
    if (lin >= UNITS * INSZ) return;
    int o = lin & (UNITS - 1);
    int i = lin >> 9;
    float sc = scale[(size_t)i * UNITS + o];

    __nv_bfloat16 c[8];
#pragma unroll
    for (int k = 0; k < 8; k++)
        c[k] = __float2bfloat16(sc * Wk[((size_t)i * 8 + k) * UNITS + o]);
    __nv_bfloat16 schi = __float2bfloat16(sc);
    __nv_bfloat16 sclo = __float2bfloat16(sc - __bfloat162float(schi));

    uint2* dst = (uint2*)(g_Bt + (size_t)o * KDIM + i * K12);
    dst[0] = make_uint2(pkb(c[0], c[1]), pkb(c[2], c[3]));
    dst[1] = make_uint2(pkb(c[4], c[5]), pkb(c[6], c[7]));
    dst[2] = make_uint2(pkb(schi, sclo), pkb(schi, __float2bfloat16(0.f)));
}

// ---------------- kernel 3: out[b,o] = bias[o] (atomic accumulation base) ----------------
__global__ void init_out(const float* __restrict__ bias, float* __restrict__ out) {
    int idx = (blockIdx.x * blockDim.x + threadIdx.x) * 4;
    if (idx >= BATCH * UNITS) return;
    *(float4*)(out + idx) = *(const float4*)(bias + (idx & (UNITS - 1)));
}

// ---------------- kernel 4: split-K bf16 mma.sync GEMM, chunk-pipelined, epilogue red.global.add ----------------
// CTA tile 128x128, 8 warps (warp tile 32x64), K-stage 64, PIPE=4 cp.async.
// Register double-buffered k16-chunk pipeline: LDSM of chunk c+1 overlaps HMMA of chunk c,
// including cross-stage prefetch of (s+1, chunk 0) before stage s's last MMA.
// Safety: CP_WAIT(1)+barrier at iter s guarantees stages <= s+2 complete AND visible to all
// threads; buffer (s+1)%4 is not refilled until after barrier(s+2) (two barriers later).
// issue_stage(s+4) after barrier(s) writes buffer s%4, whose last reads precede barrier(s).
__global__ __launch_bounds__(256, 1)
void kan_gemm(float* __restrict__ out) {
    extern __shared__ char dyn[];
    const uint32_t base = smem_u32(dyn);   // PIPE stages of [A 16KB | B 16KB]

    const int t   = threadIdx.x;
    const int wid = t >> 5, lane = t & 31;
    const int wm  = wid & 3;               // 4 warp-rows  -> 32 m each
    const int wn  = wid >> 2;              // 2 warp-cols  -> 64 n each
    const int m0  = blockIdx.y * 128;
    const int n0  = blockIdx.x * 128;
    const int kbase = blockIdx.z * KPER;

    // ---- cp.async addressing ----
    const int crow = t >> 3;               // 0..31
    const int cchk = t & 7;                // 16B chunk
    const __nv_bfloat16* gA = g_A  + (size_t)(m0 + crow) * KDIM + kbase + cchk * 8;
    const __nv_bfloat16* gB = g_Bt + (size_t)(n0 + crow) * KDIM + kbase + cchk * 8;

    auto stage_base = [&](int s) { return base + (uint32_t)(s % PIPE) * 32768u; };

    auto issue_stage = [&](int s) {
        uint32_t sb = stage_base(s);
        const __nv_bfloat16* pa = gA + s * TK;
        const __nv_bfloat16* pb = gB + s * TK;
#pragma unroll
        for (int q = 0; q < 4; q++) {
            uint32_t so = swz((uint32_t)(crow + q * 32) * 128u + (uint32_t)cchk * 16u);
            cp_async16(sb + so,          pa + (size_t)(q * 32) * KDIM);
            cp_async16(sb + 16384u + so, pb + (size_t)(q * 32) * KDIM);
        }
    };

    // ---- prologue: fill all PIPE buffers ----
#pragma unroll
    for (int s = 0; s < PIPE; s++) { issue_stage(s); CP_COMMIT(); }
    CP_WAIT(2);        // stages 0,1 complete ({2,3} outstanding)
    __syncthreads();   // ... and visible to all threads

    // ---- per-lane ldmatrix offsets ----
    const uint32_t a_row = (uint32_t)(wm * 32 + (lane & 15));
    const uint32_t a_kb  = (uint32_t)((lane >> 4) * 16);
    const uint32_t b_row = (uint32_t)(wn * 64 + (lane & 7) + ((lane >> 4) & 1) * 8);
    const uint32_t b_kb  = (uint32_t)(((lane >> 3) & 1) * 16);

    // register double-buffered fragments
    uint32_t af[2][2][4];   // [buf][mi][reg]
    uint32_t bf[2][4][4];   // [buf][g][reg]

    auto load_chunk = [&](int buf, uint32_t sa, int kk) {
        uint32_t sbB = sa + 16384u;
#pragma unroll
        for (int mi = 0; mi < 2; mi++)
            ldsm_x4(af[buf][mi][0], af[buf][mi][1], af[buf][mi][2], af[buf][mi][3],
                    sa + swz((a_row + mi * 16) * 128u + a_kb + (uint32_t)kk * 32u));
#pragma unroll
        for (int g = 0; g < 4; g++)
            ldsm_x4(bf[buf][g][0], bf[buf][g][1], bf[buf][g][2], bf[buf][g][3],
                    sbB + swz((b_row + g * 16) * 128u + b_kb + (uint32_t)kk * 32u));
    };

    float acc[2][8][4];
#pragma unroll
    for (int mi = 0; mi < 2; mi++)
#pragma unroll
        for (int ni = 0; ni < 8; ni++)
#pragma unroll
            for (int r = 0; r < 4; r++) acc[mi][ni][r] = 0.f;

    auto mma_chunk = [&](int buf) {
#pragma unroll
        for (int mi = 0; mi < 2; mi++)
#pragma unroll
            for (int g = 0; g < 4; g++) {
                mma16816(acc[mi][2 * g + 0], af[buf][mi], bf[buf][g][0], bf[buf][g][1]);
                mma16816(acc[mi][2 * g + 1], af[buf][mi], bf[buf][g][2], bf[buf][g][3]);
            }
    };

    int cur = 0;
    load_chunk(0, stage_base(0), 0);   // prime chunk (0,0)

    for (int s = 0; s < STAGES; ++s) {
        uint32_t sa = stage_base(s);
        // chunks 0..2: prefetch next chunk of this stage, then MMA current
#pragma unroll
        for (int kk = 0; kk < 3; kk++) {
            load_chunk(cur ^ 1, sa, kk + 1);
            mma_chunk(cur);
            cur ^= 1;
        }
        // pipeline advance: stage s+1/+2 completeness + buffer s%4 reads done
        CP_WAIT(1);
        __syncthreads();
        if (s + PIPE < STAGES) issue_stage(s + PIPE);
        CP_COMMIT();
        // chunk 3: prefetch (s+1, chunk 0) across the stage boundary, then MMA
        if (s + 1 < STAGES) load_chunk(cur ^ 1, stage_base(s + 1), 0);
        mma_chunk(cur);
        cur ^= 1;
    }

    // ---- epilogue: atomic-accumulate fp32 tile into out (pre-initialized with bias) ----
    const int er = lane >> 2;          // 0..7
    const int ec = (lane & 3) * 2;     // 0,2,4,6
#pragma unroll
    for (int mi = 0; mi < 2; mi++) {
#pragma unroll
        for (int ni = 0; ni < 8; ni++) {
            int row = m0 + wm * 32 + mi * 16 + er;
            int col = n0 + wn * 64 + ni * 8 + ec;
            float* p0 = out + (size_t)row * UNITS + col;
            red_add_f32(p0 + 0, acc[mi][ni][0]);
            red_add_f32(p0 + 1, acc[mi][ni][1]);
            float* p1 = p0 + 8 * UNITS;
            red_add_f32(p1 + 0, acc[mi][ni][2]);
            red_add_f32(p1 + 1, acc[mi][ni][3]);
        }
    }
}

// ---------------- launch ----------------
extern "C" void kernel_launch(void* const* d_in, const int* in_sizes, int n_in,
                              void* d_out, int out_size) {
    const float* x    = (const float*)d_in[0];  // (1024, 512)
    const float* wk   = (const float*)d_in[1];  // (512, 8, 512)
    const float* sc   = (const float*)d_in[2];  // (512, 512)
    const float* bias = (const float*)d_in[3];  // (512,)
    float* out = (float*)d_out;                 // (1024, 512)

    build_A<<<(BATCH * INSZ) / 256, 256>>>(x);
    build_Bt<<<(UNITS * INSZ) / 256, 256>>>(wk, sc);
    init_out<<<(BATCH * UNITS / 4) / 256, 256>>>(bias, out);

    const int dsmem = PIPE * 32768;  // 128 KB: 4 stages of [A 16KB | B 16KB]
    cudaFuncSetAttribute(kan_gemm, cudaFuncAttributeMaxDynamicSharedMemorySize, dsmem);
    kan_gemm<<<dim3(UNITS / 128, BATCH / 128, KSPLIT), 256, dsmem>>>(out);
}

// round 8
// speedup vs baseline: 1.2328x; 1.0119x over previous
#include <cuda_runtime.h>
#include <cuda_bf16.h>
#include <cstdint>

// ---------------- problem constants ----------------
#define BATCH  1024
#define INSZ   512
#define UNITS  512
#define K12    12
#define KDIM   (INSZ * K12)      // 6144
#define KSPLIT 4
#define KPER   (KDIM / KSPLIT)   // 1536
#define TK     64                // K columns per stage (128 B/row bf16)
#define STAGES (KPER / TK)       // 24
#define PIPE   4                 // cp.async pipeline depth

// prep kernel block-range dispatch (256 threads each)
#define PREP_A_BLOCKS   ((BATCH * INSZ) / 256)        // 2048
#define PREP_BT_BLOCKS  ((UNITS * INSZ) / 256)        // 1024
#define PREP_OUT_BLOCKS ((BATCH * UNITS / 4) / 256)   // 512

// ---------------- scratch (static device globals; no allocation) ----------------
__device__ __align__(16) __nv_bfloat16 g_A[(size_t)BATCH * KDIM];     // 12.6 MB
__device__ __align__(16) __nv_bfloat16 g_Bt[(size_t)UNITS * KDIM];    // 6.3 MB

// ---------------- helpers ----------------
__device__ __forceinline__ uint32_t smem_u32(const void* p) {
    uint32_t a;
    asm("{ .reg .u64 t; cvta.to.shared.u64 t, %1; cvt.u32.u64 %0, t; }" : "=r"(a) : "l"(p));
    return a;
}
__device__ __forceinline__ uint32_t swz(uint32_t off) { return off ^ ((off >> 3) & 0x70); }

__device__ __forceinline__ void cp_async16(uint32_t saddr, const void* g) {
    asm volatile("cp.async.cg.shared.global [%0], [%1], 16;" :: "r"(saddr), "l"(g) : "memory");
}
#define CP_COMMIT() asm volatile("cp.async.commit_group;" ::: "memory")
#define CP_WAIT(N)  asm volatile("cp.async.wait_group %0;" :: "n"(N) : "memory")

__device__ __forceinline__ void ldsm_x4(uint32_t& r0, uint32_t& r1, uint32_t& r2, uint32_t& r3,
                                        uint32_t addr) {
    asm volatile("ldmatrix.sync.aligned.m8n8.x4.shared.b16 {%0,%1,%2,%3}, [%4];"
                 : "=r"(r0), "=r"(r1), "=r"(r2), "=r"(r3) : "r"(addr));
}
__device__ __forceinline__ void mma16816(float* c, const uint32_t* a, uint32_t b0, uint32_t b1) {
    asm volatile("mma.sync.aligned.m16n8k16.row.col.f32.bf16.bf16.f32 "
                 "{%0,%1,%2,%3}, {%4,%5,%6,%7}, {%8,%9}, {%0,%1,%2,%3};"
                 : "+f"(c[0]), "+f"(c[1]), "+f"(c[2]), "+f"(c[3])
                 : "r"(a[0]), "r"(a[1]), "r"(a[2]), "r"(a[3]), "r"(b0), "r"(b1));
}
__device__ __forceinline__ void red_add_f32(float* p, float v) {
    asm volatile("red.global.add.f32 [%0], %1;" :: "l"(p), "f"(v) : "memory");
}
__device__ __forceinline__ unsigned pkb(__nv_bfloat16 a, __nv_bfloat16 b) {
    return (unsigned)__bfloat16_as_ushort(a) | ((unsigned)__bfloat16_as_ushort(b) << 16);
}

// ---------------- fused prep kernel: build_A | build_Bt | init_out by block range ----------------
__global__ void prep(const float* __restrict__ X, const float* __restrict__ Wk,
                     const float* __restrict__ scale, const float* __restrict__ bias,
                     float* __restrict__ out) {
    int blk = blockIdx.x;
    if (blk < PREP_A_BLOCKS) {
        // ---- build_A: A[b, i*12 + c] = {8 cubic B-spline bases, shi, shi, slo, 0} ----
        int lin = blk * 256 + threadIdx.x;
        float x = X[lin];
        // uniform knots t_j = -2.2 + 0.4*j (GRID=5, ORDER=3, range [-1,1])
        float bb[11];
#pragma unroll
        for (int j = 0; j < 11; j++) {
            float tj = -2.2f + 0.4f * j;
            bb[j] = (x >= tj && x < tj + 0.4f) ? 1.f : 0.f;
        }
#pragma unroll
        for (int k = 1; k <= 3; k++) {
            float inv = 1.f / (0.4f * k);
#pragma unroll
            for (int j = 0; j < 11 - k; j++) {
                float tj = -2.2f + 0.4f * j;
                float tjk1 = -2.2f + 0.4f * (j + k + 1);
                bb[j] = (x - tj) * inv * bb[j] + (tjk1 - x) * inv * bb[j + 1];
            }
        }
        float s = x / (1.f + expf(-x));  // silu
        __nv_bfloat16 shi = __float2bfloat16(s);
        __nv_bfloat16 slo = __float2bfloat16(s - __bfloat162float(shi));
        __nv_bfloat16 h[8];
#pragma unroll
        for (int j = 0; j < 8; j++) h[j] = __float2bfloat16(bb[j]);
        uint2* dst = (uint2*)(g_A + (size_t)lin * K12);
        dst[0] = make_uint2(pkb(h[0], h[1]), pkb(h[2], h[3]));
        dst[1] = make_uint2(pkb(h[4], h[5]), pkb(h[6], h[7]));
        dst[2] = make_uint2(pkb(shi, shi), pkb(slo, __float2bfloat16(0.f)));
    } else if (blk < PREP_A_BLOCKS + PREP_BT_BLOCKS) {
        // ---- build_Bt: Bt[o, i*12 + c] = {scale*W_k, schi, sclo, schi, 0} ----
        int lin = (blk - PREP_A_BLOCKS) * 256 + threadIdx.x;
        int o = lin & (UNITS - 1);
        int i = lin >> 9;
        float sc = scale[(size_t)i * UNITS + o];
        __nv_bfloat16 c[8];
#pragma unroll
        for (int k = 0; k < 8; k++)
            c[k] = __float2bfloat16(sc * Wk[((size_t)i * 8 + k) * UNITS + o]);
        __nv_bfloat16 schi = __float2bfloat16(sc);
        __nv_bfloat16 sclo = __float2bfloat16(sc - __bfloat162float(schi));
        uint2* dst = (uint2*)(g_Bt + (size_t)o * KDIM + i * K12);
        dst[0] = make_uint2(pkb(c[0], c[1]), pkb(c[2], c[3]));
        dst[1] = make_uint2(pkb(c[4], c[5]), pkb(c[6], c[7]));
        dst[2] = make_uint2(pkb(schi, sclo), pkb(schi, __float2bfloat16(0.f)));
    } else {
        // ---- init_out: out[b,o] = bias[o] ----
        int idx = ((blk - PREP_A_BLOCKS - PREP_BT_BLOCKS) * 256 + threadIdx.x) * 4;
        *(float4*)(out + idx) = *(const float4*)(bias + (idx & (UNITS - 1)));
    }
}

// ---------------- GEMM: CTA 128x128, 4 warps (64x64 each, 2x2 grid), K-stage 64, PIPE=4 ----------------
// Minimal-crossbar warp grid: LDSM traffic/stage = 2|A| + 2|B| = 64KB (+32KB STS) < tensor floor.
// Register double-buffered k16-chunk pipeline with cross-stage prefetch (proven-safe ordering:
// CP_WAIT(1)+barrier at iter s => stages <= s+2 complete+visible; buffer (s+1)%4 refilled only
// after barrier(s+2); issue_stage(s+4) after barrier(s) writes buffer s%4 whose reads are done).
__global__ __launch_bounds__(128, 1)
void kan_gemm(float* __restrict__ out) {
    extern __shared__ char dyn[];
    const uint32_t base = smem_u32(dyn);   // PIPE stages of [A 16KB | B 16KB]

    const int t    = threadIdx.x;
    const int wid  = t >> 5, lane = t & 31;
    const int wm   = wid & 1;              // 2 warp-rows -> 64 m each
    const int wn   = wid >> 1;             // 2 warp-cols -> 64 n each
    const int m0   = blockIdx.y * 128;
    const int n0   = blockIdx.x * 128;
    const int kbase = blockIdx.z * KPER;

    // ---- cp.async addressing: 128 threads, 16 rows/round, 8 rounds each for A and B ----
    const int crow = t >> 3;               // 0..15
    const int cchk = t & 7;                // 16B chunk
    const __nv_bfloat16* gA = g_A  + (size_t)(m0 + crow) * KDIM + kbase + cchk * 8;
    const __nv_bfloat16* gB = g_Bt + (size_t)(n0 + crow) * KDIM + kbase + cchk * 8;

    auto stage_base = [&](int s) { return base + (uint32_t)(s % PIPE) * 32768u; };

    auto issue_stage = [&](int s) {
        uint32_t sb = stage_base(s);
        const __nv_bfloat16* pa = gA + s * TK;
        const __nv_bfloat16* pb = gB + s * TK;
#pragma unroll
        for (int q = 0; q < 8; q++) {
            uint32_t so = swz((uint32_t)(crow + q * 16) * 128u + (uint32_t)cchk * 16u);
            cp_async16(sb + so,          pa + (size_t)(q * 16) * KDIM);
            cp_async16(sb + 16384u + so, pb + (size_t)(q * 16) * KDIM);
        }
    };

    // ---- prologue: fill all PIPE buffers ----
#pragma unroll
    for (int s = 0; s < PIPE; s++) { issue_stage(s); CP_COMMIT(); }
    CP_WAIT(2);        // stages 0,1 complete
    __syncthreads();   // ... and visible

    // ---- per-lane ldmatrix offsets ----
    const uint32_t a_row = (uint32_t)(wm * 64 + (lane & 15));
    const uint32_t a_kb  = (uint32_t)((lane >> 4) * 16);
    const uint32_t b_row = (uint32_t)(wn * 64 + (lane & 7) + ((lane >> 4) & 1) * 8);
    const uint32_t b_kb  = (uint32_t)(((lane >> 3) & 1) * 16);

    // register double-buffered fragments
    uint32_t af[2][4][4];   // [buf][mi][reg]   4 x m16
    uint32_t bf[2][4][4];   // [buf][g][reg]    4 x n16

    auto load_chunk = [&](int buf, uint32_t sa, int kk) {
        uint32_t sbB = sa + 16384u;
#pragma unroll
        for (int mi = 0; mi < 4; mi++)
            ldsm_x4(af[buf][mi][0], af[buf][mi][1], af[buf][mi][2], af[buf][mi][3],
                    sa + swz((a_row + mi * 16) * 128u + a_kb + (uint32_t)kk * 32u));
#pragma unroll
        for (int g = 0; g < 4; g++)
            ldsm_x4(bf[buf][g][0], bf[buf][g][1], bf[buf][g][2], bf[buf][g][3],
                    sbB + swz((b_row + g * 16) * 128u + b_kb + (uint32_t)kk * 32u));
    };

    float acc[4][8][4];
#pragma unroll
    for (int mi = 0; mi < 4; mi++)
#pragma unroll
        for (int ni = 0; ni < 8; ni++)
#pragma unroll
            for (int r = 0; r < 4; r++) acc[mi][ni][r] = 0.f;

    auto mma_chunk = [&](int buf) {
#pragma unroll
        for (int mi = 0; mi < 4; mi++)
#pragma unroll
            for (int g = 0; g < 4; g++) {
                mma16816(acc[mi][2 * g + 0], af[buf][mi], bf[buf][g][0], bf[buf][g][1]);
                mma16816(acc[mi][2 * g + 1], af[buf][mi], bf[buf][g][2], bf[buf][g][3]);
            }
    };

    int cur = 0;
    load_chunk(0, stage_base(0), 0);   // prime chunk (0,0)

    for (int s = 0; s < STAGES; ++s) {
        uint32_t sa = stage_base(s);
#pragma unroll
        for (int kk = 0; kk < 3; kk++) {
            load_chunk(cur ^ 1, sa, kk + 1);
            mma_chunk(cur);
            cur ^= 1;
        }
        CP_WAIT(1);
        __syncthreads();
        if (s + PIPE < STAGES) issue_stage(s + PIPE);
        CP_COMMIT();
        if (s + 1 < STAGES) load_chunk(cur ^ 1, stage_base(s + 1), 0);
        mma_chunk(cur);
        cur ^= 1;
    }

    // ---- epilogue: atomic-accumulate fp32 tile into out (pre-initialized with bias) ----
    const int er = lane >> 2;          // 0..7
    const int ec = (lane & 3) * 2;     // 0,2,4,6
#pragma unroll
    for (int mi = 0; mi < 4; mi++) {
#pragma unroll
        for (int ni = 0; ni < 8; ni++) {
            int row = m0 + wm * 64 + mi * 16 + er;
            int col = n0 + wn * 64 + ni * 8 + ec;
            float* p0 = out + (size_t)row * UNITS + col;
            red_add_f32(p0 + 0, acc[mi][ni][0]);
            red_add_f32(p0 + 1, acc[mi][ni][1]);
            float* p1 = p0 + 8 * UNITS;
            red_add_f32(p1 + 0, acc[mi][ni][2]);
            red_add_f32(p1 + 1, acc[mi][ni][3]);
        }
    }
}

// ---------------- launch ----------------
extern "C" void kernel_launch(void* const* d_in, const int* in_sizes, int n_in,
                              void* d_out, int out_size) {
    const float* x    = (const float*)d_in[0];  // (1024, 512)
    const float* wk   = (const float*)d_in[1];  // (512, 8, 512)
    const float* sc   = (const float*)d_in[2];  // (512, 512)
    const float* bias = (const float*)d_in[3];  // (512,)
    float* out = (float*)d_out;                 // (1024, 512)

    prep<<<PREP_A_BLOCKS + PREP_BT_BLOCKS + PREP_OUT_BLOCKS, 256>>>(x, wk, sc, bias, out);

    const int dsmem = PIPE * 32768;  // 128 KB: 4 stages of [A 16KB | B 16KB]
    cudaFuncSetAttribute(kan_gemm, cudaFuncAttributeMaxDynamicSharedMemorySize, dsmem);
    kan_gemm<<<dim3(UNITS / 128, BATCH / 128, KSPLIT), 128, dsmem>>>(out);
}